// round 15
// baseline (speedup 1.0000x reference)
#include <cuda_runtime.h>
#include <math.h>

// ---------------------------------------------------------------------------
// Problem constants
// ---------------------------------------------------------------------------
constexpr int H_    = 93;
constexpr int W_    = 44;
constexpr int HW_   = H_ * W_;      // 4092
constexpr int B_    = 8;
constexpr int HID_  = 128;
constexpr int LAT_  = 1024;
constexpr int MAXN_ = 24;
constexpr int OFF1  = B_ * HW_ * 2; // 65472  (mask_indices start, as float)
constexpr int OFF2  = 2 * OFF1;     // 130944 (valid_mask start, as float)
constexpr int NT4   = 8256;         // border warp-tasks (1032 positions x 8 b)

// ---------------------------------------------------------------------------
// Scratch (__device__ globals: no allocation allowed)
// ---------------------------------------------------------------------------
__device__ __align__(16) float g_T   [B_ * 9 * HID_];   // taps
__device__ __align__(16) float g_s25 [B_ * 25];
__device__ __align__(16) float g_Y   [B_ * 25 * HID_];
__device__ __align__(16) float g_base[B_ * HID_];
__device__ int g_slot[B_ * HW_];                        // packed slot or -1
__device__ unsigned g_bar;                              // monotonic barrier

__device__ __forceinline__ float gelu_(float x) {
    return 0.5f * x * (1.0f + erff(x * 0.70710678118654752440f));
}

// rowmap[out_row_class][tap] -> input row-class (0=top,1=mid,2=bot), -1 = OOB
__constant__ int c_map[5][3] = {
    {-1, 0, 1}, { 0, 1, 1}, { 1, 1, 1}, { 1, 1, 2}, { 1, 2,-1},
};

// monotone class maps (row: H=93, col: W=44)
__device__ __forceinline__ int cls_row(int rr) {
    return (rr == 0) ? 0 : (rr == 1) ? 1 : (rr == H_ - 2) ? 3 : (rr == H_ - 1) ? 4 : 2;
}
__device__ __forceinline__ int cls_col(int cc) {
    return (cc == 0) ? 0 : (cc == 1) ? 1 : (cc == W_ - 2) ? 3 : (cc == W_ - 1) ? 4 : 2;
}

// ---------------------------------------------------------------------------
// Software grid barrier (monotonic counter; grid == #SMs, occupancy 1)
// ---------------------------------------------------------------------------
__device__ __forceinline__ void grid_bar() {
    __syncthreads();
    if (threadIdx.x == 0) {
        __threadfence();
        unsigned old = atomicAdd(&g_bar, 1u);
        unsigned target = old - (old % gridDim.x) + gridDim.x;
        while (*(volatile unsigned*)&g_bar < target) { __nanosleep(32); }
        __threadfence();
    }
    __syncthreads();
}

// ---------------------------------------------------------------------------
// Shared memory union (max member ~42.3 KB < 48 KB static limit)
// ---------------------------------------------------------------------------
union __align__(16) SmemU {
    struct {                              // phase A
        float redP[32][HID_];             // 16 KB flat partials
        float s_lc[HID_];
        int   wsum[32];
    } pa;
    struct {                              // phase B (dual-batch)
        float g9b[2][9 * HID_];           // 9 KB
        float redB[2][32][HID_];          // 32 KB
        float F25s[2][HID_];
        float sred[2][4];
    } pb;
    struct {                              // phase C
        float wc[32][25];
        float sPint[8][2];
    } pc;
};

// ---------------------------------------------------------------------------
// The one persistent kernel — 3 phases, 2 grid barriers
// ---------------------------------------------------------------------------
__global__ __launch_bounds__(1024, 1) void kFused(
    const float* __restrict__ lat,  const int* __restrict__ mask,
    const int* __restrict__ nidx,   const int* __restrict__ ncnt,
    const float* __restrict__ Wl,   const float* __restrict__ bl,
    const float* __restrict__ Wt,   const float* __restrict__ bt,
    const float* __restrict__ g1,   const float* __restrict__ b1g,
    const float* __restrict__ Wc,   const float* __restrict__ bc,
    const float* __restrict__ Wa,   const float* __restrict__ ba,
    const float* __restrict__ W1,   const float* __restrict__ b1,
    const float* __restrict__ W2,   const float* __restrict__ b2,
    float* __restrict__ out) {

    __shared__ SmemU su;
    const int tid  = threadIdx.x;
    const int blk  = blockIdx.x;
    const int grid = gridDim.x;
    const int lane = tid & 31;
    const int s    = tid >> 5;      // warp id

    // =====================================================================
    // Phase A: 88 tasks, 1 wave.
    //   t <  72: (b, tap): recompute lc in-block, then tap GEMV -> g_T
    //   t <  80: (b): recompute lc, then base GEMV (W1[128:]) -> g_base
    //   t <  88: (b): mask scan + output init + g_slot
    // =====================================================================
    for (int t = blk; t < 88; t += grid) {
        if (t < 80) {
            int b, tp;
            if (t < 72) { b = t / 9; tp = t % 9; }
            else        { b = t - 72; tp = -1;   }

            // --- lc = gelu(lat[b] @ Wl + bl), warp s does i in [s*32,(s+1)*32)
            {
                const float* xb  = lat + b * LAT_ + s * 32;
                const float* wbl = Wl + (size_t)(s * 32) * HID_ + lane * 4;
                float4 accA = make_float4(0.f, 0.f, 0.f, 0.f);
                float4 accB = make_float4(0.f, 0.f, 0.f, 0.f);
                #pragma unroll 8
                for (int k = 0; k < 32; k += 2) {
                    float xk0 = xb[k], xk1 = xb[k + 1];
                    float4 w0 = *(const float4*)(wbl + (size_t)k * HID_);
                    float4 w1 = *(const float4*)(wbl + (size_t)(k + 1) * HID_);
                    accA.x = fmaf(xk0, w0.x, accA.x);
                    accA.y = fmaf(xk0, w0.y, accA.y);
                    accA.z = fmaf(xk0, w0.z, accA.z);
                    accA.w = fmaf(xk0, w0.w, accA.w);
                    accB.x = fmaf(xk1, w1.x, accB.x);
                    accB.y = fmaf(xk1, w1.y, accB.y);
                    accB.z = fmaf(xk1, w1.z, accB.z);
                    accB.w = fmaf(xk1, w1.w, accB.w);
                }
                accA.x += accB.x; accA.y += accB.y;
                accA.z += accB.z; accA.w += accB.w;
                *(float4*)&su.pa.redP[s][lane * 4] = accA;
            }
            __syncthreads();
            if (tid < HID_) {
                float v = 0.f;
                #pragma unroll
                for (int w = 0; w < 32; w++) v += su.pa.redP[w][tid];
                su.pa.s_lc[tid] = gelu_(v + bl[tid]);
            }
            __syncthreads();

            // --- second GEMV: tap (Wt[tp]) or base (W1[128:] + b1)
            {
                float4 x4 = *(const float4*)&su.pa.s_lc[s * 4];
                const float* wb2 = (tp >= 0)
                    ? Wt + (size_t)tp * HID_ * HID_ + (size_t)(s * 4) * HID_ + lane * 4
                    : W1 + (size_t)(HID_ + s * 4) * HID_ + lane * 4;
                float4 acc2 = make_float4(0.f, 0.f, 0.f, 0.f);
                #pragma unroll
                for (int k = 0; k < 4; k++) {
                    float xk = (&x4.x)[k];
                    float4 w = *(const float4*)(wb2 + (size_t)k * HID_);
                    acc2.x = fmaf(xk, w.x, acc2.x);
                    acc2.y = fmaf(xk, w.y, acc2.y);
                    acc2.z = fmaf(xk, w.z, acc2.z);
                    acc2.w = fmaf(xk, w.w, acc2.w);
                }
                *(float4*)&su.pa.redP[s][lane * 4] = acc2;
            }
            __syncthreads();
            if (tid < HID_) {
                float v = 0.f;
                #pragma unroll
                for (int w = 0; w < 32; w++) v += su.pa.redP[w][tid];
                if (tp >= 0) g_T[(b * 9 + tp) * HID_ + tid] = v;
                else         g_base[b * HID_ + tid] = v + b1[tid];
            }
            __syncthreads();
        } else {
            // --- scan task for batch b
            int b = t - 80;
            int warp = s;
            int base = tid * 4;
            int m[4], loc[4];
            int sc = 0;
            for (int j = 0; j < 4; j++) {
                int p = base + j;
                int mm = (p < HW_) ? (mask[b * HW_ + p] > 0) : 0;
                m[j] = mm; loc[j] = sc; sc += mm;
            }
            int v = sc;
            for (int off = 1; off < 32; off <<= 1) {
                int u = __shfl_up_sync(0xffffffffu, v, off);
                if (lane >= off) v += u;
            }
            if (lane == 31) su.pa.wsum[warp] = v;
            __syncthreads();
            if (warp == 0) {
                int wv = su.pa.wsum[lane];
                for (int off = 1; off < 32; off <<= 1) {
                    int u = __shfl_up_sync(0xffffffffu, wv, off);
                    if (lane >= off) wv += u;
                }
                su.pa.wsum[lane] = wv;
            }
            __syncthreads();
            int excl = (v - sc) + (warp > 0 ? su.pa.wsum[warp - 1] : 0);
            int nm = su.pa.wsum[31];

            for (int j = 0; j < 4; j++) {
                int p = base + j;
                if (p < HW_) {
                    if (m[j]) {
                        int slot = excl + loc[j];
                        out[OFF1 + (b * HW_ + slot) * 2]     = (float)(p / W_);
                        out[OFF1 + (b * HW_ + slot) * 2 + 1] = (float)(p % W_);
                        g_slot[b * HW_ + p] = slot;
                    } else {
                        g_slot[b * HW_ + p] = -1;
                    }
                }
            }
            for (int sl = nm + tid; sl < HW_; sl += 1024) {
                out[(b * HW_ + sl) * 2]            = 0.f;
                out[(b * HW_ + sl) * 2 + 1]        = 0.f;
                out[OFF1 + (b * HW_ + sl) * 2]     = 0.f;
                out[OFF1 + (b * HW_ + sl) * 2 + 1] = 0.f;
            }
            for (int sl = tid; sl < HW_; sl += 1024)
                out[OFF2 + b * HW_ + sl] = (sl < nm) ? 1.f : 0.f;
        }
    }
    grid_bar();

    // =====================================================================
    // Phase B: 100 tasks (cls x b-pair), 1 wave, DUAL-BATCH:
    //   every Wc / W1 float4 load feeds BOTH batches (2x fewer LDG).
    //   GN(2b) -> conv2 -> F25 (smem) -> s25 + Y.
    // =====================================================================
    if (blk < 100) {
        const int t   = blk;
        const int cls = t >> 2, bp = t & 3;
        const int b0  = bp * 2;
        const int orc = cls / 5, occ = cls % 5;

        // --- GN for the 2 batches (threads 0..255)
        if (tid < 256) {
            int bb = tid >> 7, o = tid & 127;
            int b = b0 + bb;
            float Tl[9];
            #pragma unroll
            for (int t9 = 0; t9 < 9; t9++) Tl[t9] = g_T[(b * 9 + t9) * HID_ + o];
            float btv = bt[o];

            float c9[9];
            for (int rc = 0; rc < 3; rc++)
                for (int cc = 0; cc < 3; cc++) {
                    float sum = btv;
                    for (int kh = 0; kh < 3; kh++) {
                        if ((rc == 0 && kh == 0) || (rc == 2 && kh == 2)) continue;
                        for (int kw = 0; kw < 3; kw++) {
                            if ((cc == 0 && kw == 0) || (cc == 2 && kw == 2)) continue;
                            sum += Tl[kh * 3 + kw];
                        }
                    }
                    c9[rc * 3 + cc] = sum;
                }

            const float rowcnt[3] = {1.f, (float)(H_ - 2), 1.f};
            const float colcnt[3] = {1.f, (float)(W_ - 2), 1.f};
            float area[9];
            for (int rc = 0; rc < 3; rc++)
                for (int cc = 0; cc < 3; cc++)
                    area[rc * 3 + cc] = rowcnt[rc] * colcnt[cc];

            const float inv = 1.0f / (16.0f * (float)HW_);
            float sm = 0.f;
            for (int k = 0; k < 9; k++) sm += area[k] * c9[k];
            for (int off = 8; off >= 1; off >>= 1) sm += __shfl_xor_sync(0xffffffffu, sm, off);
            float mean = sm * inv;

            float d = 0.f;
            for (int k = 0; k < 9; k++) { float tt2 = c9[k] - mean; d += area[k] * tt2 * tt2; }
            for (int off = 8; off >= 1; off >>= 1) d += __shfl_xor_sync(0xffffffffu, d, off);
            float rstd = rsqrtf(d * inv + 1e-5f);

            float ga = g1[o], be = b1g[o];
            for (int k = 0; k < 9; k++)
                su.pb.g9b[bb][k * HID_ + o] = gelu_((c9[k] - mean) * rstd * ga + be);
        }
        __syncthreads();

        // --- conv2 dual-batch: warp s handles i in [s*4, s*4+4), one Wc
        //     load drives both batches' accumulators.
        {
            float4 a0 = make_float4(0.f, 0.f, 0.f, 0.f);
            float4 a1 = make_float4(0.f, 0.f, 0.f, 0.f);
            for (int kh = 0; kh < 3; kh++) {
                int ir = c_map[orc][kh];
                if (ir < 0) continue;
                for (int kw = 0; kw < 3; kw++) {
                    int ic = c_map[occ][kw];
                    if (ic < 0) continue;
                    const float* g0 = su.pb.g9b[0] + (ir * 3 + ic) * HID_ + s * 4;
                    const float* g1v = su.pb.g9b[1] + (ir * 3 + ic) * HID_ + s * 4;
                    const float* wb = Wc + ((size_t)(kh * 3 + kw) * HID_ + s * 4) * HID_ + lane * 4;
                    #pragma unroll
                    for (int k = 0; k < 4; k++) {
                        float4 w = *(const float4*)(wb + (size_t)k * HID_);
                        float gk0 = g0[k], gk1 = g1v[k];
                        a0.x = fmaf(gk0, w.x, a0.x); a0.y = fmaf(gk0, w.y, a0.y);
                        a0.z = fmaf(gk0, w.z, a0.z); a0.w = fmaf(gk0, w.w, a0.w);
                        a1.x = fmaf(gk1, w.x, a1.x); a1.y = fmaf(gk1, w.y, a1.y);
                        a1.z = fmaf(gk1, w.z, a1.z); a1.w = fmaf(gk1, w.w, a1.w);
                    }
                }
            }
            *(float4*)&su.pb.redB[0][s][lane * 4] = a0;
            *(float4*)&su.pb.redB[1][s][lane * 4] = a1;
        }
        __syncthreads();
        if (tid < 256) {
            int bb = tid >> 7, o = tid & 127;
            float v = 0.f;
            #pragma unroll
            for (int w = 0; w < 32; w++) v += su.pb.redB[bb][w][o];
            su.pb.F25s[bb][o] = gelu_(v + bc[o]);
        }
        __syncthreads();

        // --- s25 partials (warps 0..7)
        if (s < 8) {
            int bb = s >> 2, ch = s & 3;
            float v = su.pb.F25s[bb][ch * 32 + lane] * Wa[ch * 32 + lane];
            for (int off = 16; off >= 1; off >>= 1)
                v += __shfl_xor_sync(0xffffffffu, v, off);
            if (lane == 0) su.pb.sred[bb][ch] = v;
        }
        // --- Y dual-batch GEMV (one W1 load per both batches)
        {
            const float* x0 = su.pb.F25s[0] + s * 4;
            const float* x1 = su.pb.F25s[1] + s * 4;
            const float* wb = W1 + (size_t)(s * 4) * HID_ + lane * 4;
            float4 a0 = make_float4(0.f, 0.f, 0.f, 0.f);
            float4 a1 = make_float4(0.f, 0.f, 0.f, 0.f);
            #pragma unroll
            for (int k = 0; k < 4; k++) {
                float4 w = *(const float4*)(wb + (size_t)k * HID_);
                float xk0 = x0[k], xk1 = x1[k];
                a0.x = fmaf(xk0, w.x, a0.x); a0.y = fmaf(xk0, w.y, a0.y);
                a0.z = fmaf(xk0, w.z, a0.z); a0.w = fmaf(xk0, w.w, a0.w);
                a1.x = fmaf(xk1, w.x, a1.x); a1.y = fmaf(xk1, w.y, a1.y);
                a1.z = fmaf(xk1, w.z, a1.z); a1.w = fmaf(xk1, w.w, a1.w);
            }
            *(float4*)&su.pb.redB[0][s][lane * 4] = a0;
            *(float4*)&su.pb.redB[1][s][lane * 4] = a1;
        }
        __syncthreads();
        if (tid < 256) {
            int bb = tid >> 7, o = tid & 127;
            float v = 0.f;
            #pragma unroll
            for (int w = 0; w < 32; w++) v += su.pb.redB[bb][w][o];
            g_Y[((b0 + bb) * 25 + cls) * HID_ + o] = v;
        }
        if (tid < 2)
            g_s25[(b0 + tid) * 25 + cls] = su.pb.sred[tid][0] + su.pb.sred[tid][1]
                                         + su.pb.sred[tid][2] + su.pb.sred[tid][3] + ba[0];
    }
    grid_bar();

    // =====================================================================
    // Phase C: Pint (per block), interior fill, border attention -> packed out
    //   Class accumulation iterates ONLY the position's class rectangle
    //   [cls_row(r-2..r+2)] x [cls_col(c-2..c+2)]  (monotone class maps =>
    //   present classes are a contiguous rectangle; <=9 vs 25 iterations).
    // =====================================================================
    {
        const int warp = s;
        // W2 is constant per lane across ALL tasks: load once.
        const float4 w2a = *(const float4*)&W2[lane * 8];
        const float4 w2b = *(const float4*)&W2[lane * 8 + 4];

        if (warp < 8) {
            int b = warp;
            float4 y4  = *(const float4*)&g_Y[(b * 25 + 12) * HID_ + lane * 4];
            float4 bs4 = *(const float4*)&g_base[b * HID_ + lane * 4];
            float hx = gelu_(y4.x + bs4.x), hy = gelu_(y4.y + bs4.y);
            float hz = gelu_(y4.z + bs4.z), hw = gelu_(y4.w + bs4.w);
            float p0 = hx * w2a.x + hy * w2a.z + hz * w2b.x + hw * w2b.z;
            float p1 = hx * w2a.y + hy * w2a.w + hz * w2b.y + hw * w2b.w;
            for (int off = 16; off >= 1; off >>= 1) {
                p0 += __shfl_xor_sync(0xffffffffu, p0, off);
                p1 += __shfl_xor_sync(0xffffffffu, p1, off);
            }
            if (lane == 0) {
                su.pc.sPint[b][0] = p0 + b2[0];
                su.pc.sPint[b][1] = p1 + b2[1];
            }
        }
        __syncthreads();

        // interior masked slots -> Pint
        for (int idx = blk * 1024 + tid; idx < 8 * 4096; idx += grid * 1024) {
            int b = idx >> 12, pp = idx & 4095;
            if (pp < HW_) {
                int slot = g_slot[b * HW_ + pp];
                if (slot >= 0) {
                    int r = pp / W_, c = pp % W_;
                    if (r >= 4 && r <= H_ - 5 && c >= 4 && c <= W_ - 5) {
                        out[(b * HW_ + slot) * 2]     = su.pc.sPint[b][0];
                        out[(b * HW_ + slot) * 2 + 1] = su.pc.sPint[b][1];
                    }
                }
            }
        }

        // border attention (masked positions only)
        float* wcw = su.pc.wc[warp];
        const float b20 = b2[0], b21 = b2[1];
        const int nwarp = grid * 32;
        for (int task = blk * 32 + warp; task < NT4; task += nwarp) {
            int j = task >> 3, b = task & 7;
            int r, c;
            if (j < 176)      { r = j / 44;                 c = j % 44; }
            else if (j < 352) { int j2 = j - 176; r = 89 + j2 / 44; c = j2 % 44; }
            else              { int j3 = j - 352; r = 4 + j3 / 8;
                                int k = j3 % 8; c = (k < 4) ? k : 36 + k; }
            int p = r * W_ + c;
            int slot = g_slot[b * HW_ + p];
            if (slot < 0) continue;

            if (lane < 25) wcw[lane] = 0.f;
            __syncwarp();

            bool has = lane < MAXN_;
            float logit = -3.0e38f;
            int cls = 0;
            if (has) {
                int idx = nidx[p * MAXN_ + lane];
                int rr = idx / W_, c2 = idx % W_;
                cls = cls_row(rr) * 5 + cls_col(c2);
                bool valid = (lane < ncnt[p]) && (mask[b * HW_ + idx] == 0);
                logit = valid ? g_s25[b * 25 + cls] : -10000.0f;
            }
            float m = logit;
            for (int off = 16; off >= 1; off >>= 1)
                m = fmaxf(m, __shfl_xor_sync(0xffffffffu, m, off));
            float e = has ? expf(logit - m) : 0.f;
            float se = e;
            for (int off = 16; off >= 1; off >>= 1)
                se += __shfl_xor_sync(0xffffffffu, se, off);
            float wgt = e / se;
            if (has && wgt != 0.f) atomicAdd(&wcw[cls], wgt);
            __syncwarp();

            // class rectangle for this position (warp-uniform, <=3x3)
            int rlo = r - 2; if (rlo < 0) rlo = 0;
            int rhi = r + 2; if (rhi > H_ - 1) rhi = H_ - 1;
            int clo = c - 2; if (clo < 0) clo = 0;
            int chi = c + 2; if (chi > W_ - 1) chi = W_ - 1;
            int rcl = cls_row(rlo), rch = cls_row(rhi);
            int ccl = cls_col(clo), cch = cls_col(chi);

            float4 acc = *(const float4*)&g_base[b * HID_ + lane * 4];
            for (int rc = rcl; rc <= rch; rc++) {
                for (int cc = ccl; cc <= cch; cc++) {
                    int cl = rc * 5 + cc;
                    float wv = wcw[cl];
                    if (wv != 0.f) {
                        float4 y = *(const float4*)&g_Y[(b * 25 + cl) * HID_ + lane * 4];
                        acc.x = fmaf(wv, y.x, acc.x);
                        acc.y = fmaf(wv, y.y, acc.y);
                        acc.z = fmaf(wv, y.z, acc.z);
                        acc.w = fmaf(wv, y.w, acc.w);
                    }
                }
            }
            float hx = gelu_(acc.x), hy = gelu_(acc.y), hz = gelu_(acc.z), hw = gelu_(acc.w);
            float p0 = hx * w2a.x + hy * w2a.z + hz * w2b.x + hw * w2b.z;
            float p1 = hx * w2a.y + hy * w2a.w + hz * w2b.y + hw * w2b.w;
            for (int off = 16; off >= 1; off >>= 1) {
                p0 += __shfl_xor_sync(0xffffffffu, p0, off);
                p1 += __shfl_xor_sync(0xffffffffu, p1, off);
            }
            if (lane == 0) {
                out[(b * HW_ + slot) * 2]     = p0 + b20;
                out[(b * HW_ + slot) * 2 + 1] = p1 + b21;
            }
            __syncwarp();
        }
    }
}

// ---------------------------------------------------------------------------
// kernel_launch — single persistent node
// ---------------------------------------------------------------------------
extern "C" void kernel_launch(void* const* d_in, const int* in_sizes, int n_in,
                              void* d_out, int out_size) {
    const float* latent = (const float*)d_in[1];
    const int*   mask   = (const int*)  d_in[2];
    const int*   nidx   = (const int*)  d_in[3];
    const int*   ncnt   = (const int*)  d_in[4];
    const float* Wl = (const float*)d_in[5];
    const float* bl = (const float*)d_in[6];
    const float* Wt = (const float*)d_in[7];
    const float* bt = (const float*)d_in[8];
    const float* g1 = (const float*)d_in[9];
    const float* b1g= (const float*)d_in[10];
    const float* Wc = (const float*)d_in[11];
    const float* bc = (const float*)d_in[12];
    const float* Wa = (const float*)d_in[13];
    const float* ba = (const float*)d_in[14];
    const float* W1 = (const float*)d_in[15];
    const float* b1 = (const float*)d_in[16];
    const float* W2 = (const float*)d_in[17];
    const float* b2 = (const float*)d_in[18];

    int nsm = 148;
    cudaDeviceGetAttribute(&nsm, cudaDevAttrMultiProcessorCount, 0);

    kFused<<<nsm, 1024>>>(latent, mask, nidx, ncnt,
                          Wl, bl, Wt, bt, g1, b1g, Wc, bc,
                          Wa, ba, W1, b1, W2, b2,
                          (float*)d_out);
}

// round 16
// speedup vs baseline: 1.0056x; 1.0056x over previous
#include <cuda_runtime.h>
#include <math.h>

// ---------------------------------------------------------------------------
// Problem constants
// ---------------------------------------------------------------------------
constexpr int H_    = 93;
constexpr int W_    = 44;
constexpr int HW_   = H_ * W_;      // 4092
constexpr int B_    = 8;
constexpr int HID_  = 128;
constexpr int LAT_  = 1024;
constexpr int MAXN_ = 24;
constexpr int OFF1  = B_ * HW_ * 2; // 65472  (mask_indices start, as float)
constexpr int OFF2  = 2 * OFF1;     // 130944 (valid_mask start, as float)
constexpr int NT4   = 8256;         // border warp-tasks (1032 positions x 8 b)

// ---------------------------------------------------------------------------
// Scratch (__device__ globals: no allocation allowed)
// ---------------------------------------------------------------------------
__device__ __align__(16) float g_T   [B_ * 9 * HID_];   // taps
__device__ __align__(16) float g_s25 [B_ * 25];
__device__ __align__(16) float g_Y   [B_ * 25 * HID_];
__device__ __align__(16) float g_base[B_ * HID_];
__device__ int g_slot[B_ * HW_];                        // packed slot or -1
__device__ unsigned g_bar;                              // monotonic barrier

__device__ __forceinline__ float gelu_(float x) {
    return 0.5f * x * (1.0f + erff(x * 0.70710678118654752440f));
}

// rowmap[out_row_class][tap] -> input row-class (0=top,1=mid,2=bot), -1 = OOB
__constant__ int c_map[5][3] = {
    {-1, 0, 1}, { 0, 1, 1}, { 1, 1, 1}, { 1, 1, 2}, { 1, 2,-1},
};

// monotone class maps (row: H=93, col: W=44)
__device__ __forceinline__ int cls_row(int rr) {
    return (rr == 0) ? 0 : (rr == 1) ? 1 : (rr == H_ - 2) ? 3 : (rr == H_ - 1) ? 4 : 2;
}
__device__ __forceinline__ int cls_col(int cc) {
    return (cc == 0) ? 0 : (cc == 1) ? 1 : (cc == W_ - 2) ? 3 : (cc == W_ - 1) ? 4 : 2;
}

// ---------------------------------------------------------------------------
// Software grid barrier (monotonic counter; grid == #SMs, occupancy 1)
// ---------------------------------------------------------------------------
__device__ __forceinline__ void grid_bar() {
    __syncthreads();
    if (threadIdx.x == 0) {
        __threadfence();
        unsigned old = atomicAdd(&g_bar, 1u);
        unsigned target = old - (old % gridDim.x) + gridDim.x;
        while (*(volatile unsigned*)&g_bar < target) { __nanosleep(32); }
        __threadfence();
    }
    __syncthreads();
}

// ---------------------------------------------------------------------------
// Shared memory union (max member ~42.3 KB < 48 KB static limit)
// ---------------------------------------------------------------------------
union __align__(16) SmemU {
    struct {                              // phase A (dual-batch)
        float redD[2][32][HID_];          // 32 KB partials, per batch of pair
        float s_lc2[2][HID_];
        int   wsum[32];
    } pa;
    struct {                              // phase B (dual-batch)
        float g9b[2][9 * HID_];           // 9 KB
        float redB[2][32][HID_];          // 32 KB
        float F25s[2][HID_];
        float sred[2][4];
    } pb;
    struct {                              // phase C
        float wc[32][25];
        float sPint[8][2];
    } pc;
};

// ---------------------------------------------------------------------------
// The one persistent kernel — 3 phases, 2 grid barriers
// ---------------------------------------------------------------------------
__global__ __launch_bounds__(1024, 1) void kFused(
    const float* __restrict__ lat,  const int* __restrict__ mask,
    const int* __restrict__ nidx,   const int* __restrict__ ncnt,
    const float* __restrict__ Wl,   const float* __restrict__ bl,
    const float* __restrict__ Wt,   const float* __restrict__ bt,
    const float* __restrict__ g1,   const float* __restrict__ b1g,
    const float* __restrict__ Wc,   const float* __restrict__ bc,
    const float* __restrict__ Wa,   const float* __restrict__ ba,
    const float* __restrict__ W1,   const float* __restrict__ b1,
    const float* __restrict__ W2,   const float* __restrict__ b2,
    float* __restrict__ out) {

    __shared__ SmemU su;
    const int tid  = threadIdx.x;
    const int blk  = blockIdx.x;
    const int grid = gridDim.x;
    const int lane = tid & 31;
    const int s    = tid >> 5;      // warp id

    // =====================================================================
    // Phase A: 48 tasks, 1 wave, DUAL-BATCH (one Wl/Wt/W1 load feeds a
    //   b-pair; Wl L2 traffic halved vs per-(b,tap) tasks).
    //   t < 36 : (pair, tap): lc for both batches, then tap GEMV -> g_T
    //   t < 40 : (pair): lc, then base GEMV (W1[128:]) -> g_base
    //   t < 48 : (b): mask scan + output init + g_slot
    // =====================================================================
    for (int t = blk; t < 48; t += grid) {
        if (t < 40) {
            int pair, tp;
            if (t < 36) { pair = t / 9; tp = t % 9; }
            else        { pair = t - 36; tp = -1;   }
            const int b0 = pair * 2, b1v = b0 + 1;

            // --- lc for both batches: warp s does i in [s*32,(s+1)*32)
            {
                const float* x0  = lat + b0  * LAT_ + s * 32;
                const float* x1  = lat + b1v * LAT_ + s * 32;
                const float* wbl = Wl + (size_t)(s * 32) * HID_ + lane * 4;
                float4 a0 = make_float4(0.f, 0.f, 0.f, 0.f);
                float4 a1 = make_float4(0.f, 0.f, 0.f, 0.f);
                #pragma unroll 8
                for (int k = 0; k < 32; k++) {
                    float4 w = *(const float4*)(wbl + (size_t)k * HID_);
                    float xk0 = x0[k], xk1 = x1[k];
                    a0.x = fmaf(xk0, w.x, a0.x); a0.y = fmaf(xk0, w.y, a0.y);
                    a0.z = fmaf(xk0, w.z, a0.z); a0.w = fmaf(xk0, w.w, a0.w);
                    a1.x = fmaf(xk1, w.x, a1.x); a1.y = fmaf(xk1, w.y, a1.y);
                    a1.z = fmaf(xk1, w.z, a1.z); a1.w = fmaf(xk1, w.w, a1.w);
                }
                *(float4*)&su.pa.redD[0][s][lane * 4] = a0;
                *(float4*)&su.pa.redD[1][s][lane * 4] = a1;
            }
            __syncthreads();
            if (tid < 256) {
                int bb = tid >> 7, o = tid & 127;
                float v = 0.f;
                #pragma unroll
                for (int w = 0; w < 32; w++) v += su.pa.redD[bb][w][o];
                su.pa.s_lc2[bb][o] = gelu_(v + bl[o]);
            }
            __syncthreads();

            // --- second GEMV (dual): tap (Wt[tp]) or base (W1[128:] + b1)
            {
                float4 x0 = *(const float4*)&su.pa.s_lc2[0][s * 4];
                float4 x1 = *(const float4*)&su.pa.s_lc2[1][s * 4];
                const float* wb2 = (tp >= 0)
                    ? Wt + (size_t)tp * HID_ * HID_ + (size_t)(s * 4) * HID_ + lane * 4
                    : W1 + (size_t)(HID_ + s * 4) * HID_ + lane * 4;
                float4 a0 = make_float4(0.f, 0.f, 0.f, 0.f);
                float4 a1 = make_float4(0.f, 0.f, 0.f, 0.f);
                #pragma unroll
                for (int k = 0; k < 4; k++) {
                    float4 w = *(const float4*)(wb2 + (size_t)k * HID_);
                    float xk0 = (&x0.x)[k], xk1 = (&x1.x)[k];
                    a0.x = fmaf(xk0, w.x, a0.x); a0.y = fmaf(xk0, w.y, a0.y);
                    a0.z = fmaf(xk0, w.z, a0.z); a0.w = fmaf(xk0, w.w, a0.w);
                    a1.x = fmaf(xk1, w.x, a1.x); a1.y = fmaf(xk1, w.y, a1.y);
                    a1.z = fmaf(xk1, w.z, a1.z); a1.w = fmaf(xk1, w.w, a1.w);
                }
                *(float4*)&su.pa.redD[0][s][lane * 4] = a0;
                *(float4*)&su.pa.redD[1][s][lane * 4] = a1;
            }
            __syncthreads();
            if (tid < 256) {
                int bb = tid >> 7, o = tid & 127;
                int b = b0 + bb;
                float v = 0.f;
                #pragma unroll
                for (int w = 0; w < 32; w++) v += su.pa.redD[bb][w][o];
                if (tp >= 0) g_T[(b * 9 + tp) * HID_ + o] = v;
                else         g_base[b * HID_ + o] = v + b1[o];
            }
            __syncthreads();
        } else {
            // --- scan task for batch b
            int b = t - 40;
            int warp = s;
            int base = tid * 4;
            int m[4], loc[4];
            int sc = 0;
            for (int j = 0; j < 4; j++) {
                int p = base + j;
                int mm = (p < HW_) ? (mask[b * HW_ + p] > 0) : 0;
                m[j] = mm; loc[j] = sc; sc += mm;
            }
            int v = sc;
            for (int off = 1; off < 32; off <<= 1) {
                int u = __shfl_up_sync(0xffffffffu, v, off);
                if (lane >= off) v += u;
            }
            if (lane == 31) su.pa.wsum[warp] = v;
            __syncthreads();
            if (warp == 0) {
                int wv = su.pa.wsum[lane];
                for (int off = 1; off < 32; off <<= 1) {
                    int u = __shfl_up_sync(0xffffffffu, wv, off);
                    if (lane >= off) wv += u;
                }
                su.pa.wsum[lane] = wv;
            }
            __syncthreads();
            int excl = (v - sc) + (warp > 0 ? su.pa.wsum[warp - 1] : 0);
            int nm = su.pa.wsum[31];

            for (int j = 0; j < 4; j++) {
                int p = base + j;
                if (p < HW_) {
                    if (m[j]) {
                        int slot = excl + loc[j];
                        out[OFF1 + (b * HW_ + slot) * 2]     = (float)(p / W_);
                        out[OFF1 + (b * HW_ + slot) * 2 + 1] = (float)(p % W_);
                        g_slot[b * HW_ + p] = slot;
                    } else {
                        g_slot[b * HW_ + p] = -1;
                    }
                }
            }
            for (int sl = nm + tid; sl < HW_; sl += 1024) {
                out[(b * HW_ + sl) * 2]            = 0.f;
                out[(b * HW_ + sl) * 2 + 1]        = 0.f;
                out[OFF1 + (b * HW_ + sl) * 2]     = 0.f;
                out[OFF1 + (b * HW_ + sl) * 2 + 1] = 0.f;
            }
            for (int sl = tid; sl < HW_; sl += 1024)
                out[OFF2 + b * HW_ + sl] = (sl < nm) ? 1.f : 0.f;
        }
    }
    grid_bar();

    // =====================================================================
    // Phase B: 100 tasks (cls x b-pair), 1 wave, DUAL-BATCH:
    //   every Wc / W1 float4 load feeds BOTH batches (2x fewer LDG).
    //   GN(2b) -> conv2 -> F25 (smem) -> s25 + Y.
    // =====================================================================
    if (blk < 100) {
        const int t   = blk;
        const int cls = t >> 2, bp = t & 3;
        const int b0  = bp * 2;
        const int orc = cls / 5, occ = cls % 5;

        // --- GN for the 2 batches (threads 0..255)
        if (tid < 256) {
            int bb = tid >> 7, o = tid & 127;
            int b = b0 + bb;
            float Tl[9];
            #pragma unroll
            for (int t9 = 0; t9 < 9; t9++) Tl[t9] = g_T[(b * 9 + t9) * HID_ + o];
            float btv = bt[o];

            float c9[9];
            for (int rc = 0; rc < 3; rc++)
                for (int cc = 0; cc < 3; cc++) {
                    float sum = btv;
                    for (int kh = 0; kh < 3; kh++) {
                        if ((rc == 0 && kh == 0) || (rc == 2 && kh == 2)) continue;
                        for (int kw = 0; kw < 3; kw++) {
                            if ((cc == 0 && kw == 0) || (cc == 2 && kw == 2)) continue;
                            sum += Tl[kh * 3 + kw];
                        }
                    }
                    c9[rc * 3 + cc] = sum;
                }

            const float rowcnt[3] = {1.f, (float)(H_ - 2), 1.f};
            const float colcnt[3] = {1.f, (float)(W_ - 2), 1.f};
            float area[9];
            for (int rc = 0; rc < 3; rc++)
                for (int cc = 0; cc < 3; cc++)
                    area[rc * 3 + cc] = rowcnt[rc] * colcnt[cc];

            const float inv = 1.0f / (16.0f * (float)HW_);
            float sm = 0.f;
            for (int k = 0; k < 9; k++) sm += area[k] * c9[k];
            for (int off = 8; off >= 1; off >>= 1) sm += __shfl_xor_sync(0xffffffffu, sm, off);
            float mean = sm * inv;

            float d = 0.f;
            for (int k = 0; k < 9; k++) { float tt2 = c9[k] - mean; d += area[k] * tt2 * tt2; }
            for (int off = 8; off >= 1; off >>= 1) d += __shfl_xor_sync(0xffffffffu, d, off);
            float rstd = rsqrtf(d * inv + 1e-5f);

            float ga = g1[o], be = b1g[o];
            for (int k = 0; k < 9; k++)
                su.pb.g9b[bb][k * HID_ + o] = gelu_((c9[k] - mean) * rstd * ga + be);
        }
        __syncthreads();

        // --- conv2 dual-batch: warp s handles i in [s*4, s*4+4), one Wc
        //     load drives both batches' accumulators.
        {
            float4 a0 = make_float4(0.f, 0.f, 0.f, 0.f);
            float4 a1 = make_float4(0.f, 0.f, 0.f, 0.f);
            for (int kh = 0; kh < 3; kh++) {
                int ir = c_map[orc][kh];
                if (ir < 0) continue;
                for (int kw = 0; kw < 3; kw++) {
                    int ic = c_map[occ][kw];
                    if (ic < 0) continue;
                    const float* g0 = su.pb.g9b[0] + (ir * 3 + ic) * HID_ + s * 4;
                    const float* g1v = su.pb.g9b[1] + (ir * 3 + ic) * HID_ + s * 4;
                    const float* wb = Wc + ((size_t)(kh * 3 + kw) * HID_ + s * 4) * HID_ + lane * 4;
                    #pragma unroll
                    for (int k = 0; k < 4; k++) {
                        float4 w = *(const float4*)(wb + (size_t)k * HID_);
                        float gk0 = g0[k], gk1 = g1v[k];
                        a0.x = fmaf(gk0, w.x, a0.x); a0.y = fmaf(gk0, w.y, a0.y);
                        a0.z = fmaf(gk0, w.z, a0.z); a0.w = fmaf(gk0, w.w, a0.w);
                        a1.x = fmaf(gk1, w.x, a1.x); a1.y = fmaf(gk1, w.y, a1.y);
                        a1.z = fmaf(gk1, w.z, a1.z); a1.w = fmaf(gk1, w.w, a1.w);
                    }
                }
            }
            *(float4*)&su.pb.redB[0][s][lane * 4] = a0;
            *(float4*)&su.pb.redB[1][s][lane * 4] = a1;
        }
        __syncthreads();
        if (tid < 256) {
            int bb = tid >> 7, o = tid & 127;
            float v = 0.f;
            #pragma unroll
            for (int w = 0; w < 32; w++) v += su.pb.redB[bb][w][o];
            su.pb.F25s[bb][o] = gelu_(v + bc[o]);
        }
        __syncthreads();

        // --- s25 partials (warps 0..7)
        if (s < 8) {
            int bb = s >> 2, ch = s & 3;
            float v = su.pb.F25s[bb][ch * 32 + lane] * Wa[ch * 32 + lane];
            for (int off = 16; off >= 1; off >>= 1)
                v += __shfl_xor_sync(0xffffffffu, v, off);
            if (lane == 0) su.pb.sred[bb][ch] = v;
        }
        // --- Y dual-batch GEMV (one W1 load per both batches)
        {
            const float* x0 = su.pb.F25s[0] + s * 4;
            const float* x1 = su.pb.F25s[1] + s * 4;
            const float* wb = W1 + (size_t)(s * 4) * HID_ + lane * 4;
            float4 a0 = make_float4(0.f, 0.f, 0.f, 0.f);
            float4 a1 = make_float4(0.f, 0.f, 0.f, 0.f);
            #pragma unroll
            for (int k = 0; k < 4; k++) {
                float4 w = *(const float4*)(wb + (size_t)k * HID_);
                float xk0 = x0[k], xk1 = x1[k];
                a0.x = fmaf(xk0, w.x, a0.x); a0.y = fmaf(xk0, w.y, a0.y);
                a0.z = fmaf(xk0, w.z, a0.z); a0.w = fmaf(xk0, w.w, a0.w);
                a1.x = fmaf(xk1, w.x, a1.x); a1.y = fmaf(xk1, w.y, a1.y);
                a1.z = fmaf(xk1, w.z, a1.z); a1.w = fmaf(xk1, w.w, a1.w);
            }
            *(float4*)&su.pb.redB[0][s][lane * 4] = a0;
            *(float4*)&su.pb.redB[1][s][lane * 4] = a1;
        }
        __syncthreads();
        if (tid < 256) {
            int bb = tid >> 7, o = tid & 127;
            float v = 0.f;
            #pragma unroll
            for (int w = 0; w < 32; w++) v += su.pb.redB[bb][w][o];
            g_Y[((b0 + bb) * 25 + cls) * HID_ + o] = v;
        }
        if (tid < 2)
            g_s25[(b0 + tid) * 25 + cls] = su.pb.sred[tid][0] + su.pb.sred[tid][1]
                                         + su.pb.sred[tid][2] + su.pb.sred[tid][3] + ba[0];
    }
    grid_bar();

    // =====================================================================
    // Phase C: Pint (per block), interior fill, border attention -> packed out
    //   Class accumulation iterates only the position's class rectangle.
    // =====================================================================
    {
        const int warp = s;
        // W2 is constant per lane across ALL tasks: load once.
        const float4 w2a = *(const float4*)&W2[lane * 8];
        const float4 w2b = *(const float4*)&W2[lane * 8 + 4];

        if (warp < 8) {
            int b = warp;
            float4 y4  = *(const float4*)&g_Y[(b * 25 + 12) * HID_ + lane * 4];
            float4 bs4 = *(const float4*)&g_base[b * HID_ + lane * 4];
            float hx = gelu_(y4.x + bs4.x), hy = gelu_(y4.y + bs4.y);
            float hz = gelu_(y4.z + bs4.z), hw = gelu_(y4.w + bs4.w);
            float p0 = hx * w2a.x + hy * w2a.z + hz * w2b.x + hw * w2b.z;
            float p1 = hx * w2a.y + hy * w2a.w + hz * w2b.y + hw * w2b.w;
            for (int off = 16; off >= 1; off >>= 1) {
                p0 += __shfl_xor_sync(0xffffffffu, p0, off);
                p1 += __shfl_xor_sync(0xffffffffu, p1, off);
            }
            if (lane == 0) {
                su.pc.sPint[b][0] = p0 + b2[0];
                su.pc.sPint[b][1] = p1 + b2[1];
            }
        }
        __syncthreads();

        // interior masked slots -> Pint
        for (int idx = blk * 1024 + tid; idx < 8 * 4096; idx += grid * 1024) {
            int b = idx >> 12, pp = idx & 4095;
            if (pp < HW_) {
                int slot = g_slot[b * HW_ + pp];
                if (slot >= 0) {
                    int r = pp / W_, c = pp % W_;
                    if (r >= 4 && r <= H_ - 5 && c >= 4 && c <= W_ - 5) {
                        out[(b * HW_ + slot) * 2]     = su.pc.sPint[b][0];
                        out[(b * HW_ + slot) * 2 + 1] = su.pc.sPint[b][1];
                    }
                }
            }
        }

        // border attention (masked positions only)
        float* wcw = su.pc.wc[warp];
        const float b20 = b2[0], b21 = b2[1];
        const int nwarp = grid * 32;
        for (int task = blk * 32 + warp; task < NT4; task += nwarp) {
            int j = task >> 3, b = task & 7;
            int r, c;
            if (j < 176)      { r = j / 44;                 c = j % 44; }
            else if (j < 352) { int j2 = j - 176; r = 89 + j2 / 44; c = j2 % 44; }
            else              { int j3 = j - 352; r = 4 + j3 / 8;
                                int k = j3 % 8; c = (k < 4) ? k : 36 + k; }
            int p = r * W_ + c;
            int slot = g_slot[b * HW_ + p];
            if (slot < 0) continue;

            if (lane < 25) wcw[lane] = 0.f;
            __syncwarp();

            bool has = lane < MAXN_;
            float logit = -3.0e38f;
            int cls = 0;
            if (has) {
                int idx = nidx[p * MAXN_ + lane];
                int rr = idx / W_, c2 = idx % W_;
                cls = cls_row(rr) * 5 + cls_col(c2);
                bool valid = (lane < ncnt[p]) && (mask[b * HW_ + idx] == 0);
                logit = valid ? g_s25[b * 25 + cls] : -10000.0f;
            }
            float m = logit;
            for (int off = 16; off >= 1; off >>= 1)
                m = fmaxf(m, __shfl_xor_sync(0xffffffffu, m, off));
            float e = has ? expf(logit - m) : 0.f;
            float se = e;
            for (int off = 16; off >= 1; off >>= 1)
                se += __shfl_xor_sync(0xffffffffu, se, off);
            float wgt = e / se;
            if (has && wgt != 0.f) atomicAdd(&wcw[cls], wgt);
            __syncwarp();

            // class rectangle for this position (warp-uniform, <=3x3)
            int rlo = r - 2; if (rlo < 0) rlo = 0;
            int rhi = r + 2; if (rhi > H_ - 1) rhi = H_ - 1;
            int clo = c - 2; if (clo < 0) clo = 0;
            int chi = c + 2; if (chi > W_ - 1) chi = W_ - 1;
            int rcl = cls_row(rlo), rch = cls_row(rhi);
            int ccl = cls_col(clo), cch = cls_col(chi);

            float4 acc = *(const float4*)&g_base[b * HID_ + lane * 4];
            for (int rc = rcl; rc <= rch; rc++) {
                for (int cc = ccl; cc <= cch; cc++) {
                    int cl = rc * 5 + cc;
                    float wv = wcw[cl];
                    if (wv != 0.f) {
                        float4 y = *(const float4*)&g_Y[(b * 25 + cl) * HID_ + lane * 4];
                        acc.x = fmaf(wv, y.x, acc.x);
                        acc.y = fmaf(wv, y.y, acc.y);
                        acc.z = fmaf(wv, y.z, acc.z);
                        acc.w = fmaf(wv, y.w, acc.w);
                    }
                }
            }
            float hx = gelu_(acc.x), hy = gelu_(acc.y), hz = gelu_(acc.z), hw = gelu_(acc.w);
            float p0 = hx * w2a.x + hy * w2a.z + hz * w2b.x + hw * w2b.z;
            float p1 = hx * w2a.y + hy * w2a.w + hz * w2b.y + hw * w2b.w;
            for (int off = 16; off >= 1; off >>= 1) {
                p0 += __shfl_xor_sync(0xffffffffu, p0, off);
                p1 += __shfl_xor_sync(0xffffffffu, p1, off);
            }
            if (lane == 0) {
                out[(b * HW_ + slot) * 2]     = p0 + b20;
                out[(b * HW_ + slot) * 2 + 1] = p1 + b21;
            }
            __syncwarp();
        }
    }
}

// ---------------------------------------------------------------------------
// kernel_launch — single persistent node
// ---------------------------------------------------------------------------
extern "C" void kernel_launch(void* const* d_in, const int* in_sizes, int n_in,
                              void* d_out, int out_size) {
    const float* latent = (const float*)d_in[1];
    const int*   mask   = (const int*)  d_in[2];
    const int*   nidx   = (const int*)  d_in[3];
    const int*   ncnt   = (const int*)  d_in[4];
    const float* Wl = (const float*)d_in[5];
    const float* bl = (const float*)d_in[6];
    const float* Wt = (const float*)d_in[7];
    const float* bt = (const float*)d_in[8];
    const float* g1 = (const float*)d_in[9];
    const float* b1g= (const float*)d_in[10];
    const float* Wc = (const float*)d_in[11];
    const float* bc = (const float*)d_in[12];
    const float* Wa = (const float*)d_in[13];
    const float* ba = (const float*)d_in[14];
    const float* W1 = (const float*)d_in[15];
    const float* b1 = (const float*)d_in[16];
    const float* W2 = (const float*)d_in[17];
    const float* b2 = (const float*)d_in[18];

    int nsm = 148;
    cudaDeviceGetAttribute(&nsm, cudaDevAttrMultiProcessorCount, 0);

    kFused<<<nsm, 1024>>>(latent, mask, nidx, ncnt,
                          Wl, bl, Wt, bt, g1, b1g, Wc, bc,
                          Wa, ba, W1, b1, W2, b2,
                          (float*)d_out);
}